// round 2
// baseline (speedup 1.0000x reference)
#include <cuda_runtime.h>
#include <cuda_bf16.h>
#include <math.h>

// Problem constants (fixed by the dataset)
#define BB 2
#define HH 12
#define SS 3456
#define DD 32
#define FPT 216           // feats per timestep
#define NT (SS / FPT)     // 16 timesteps
#define WIN 8
#define IMG_START 20      // FPT - img_feat_size(196)
#define JOINT_START 4     // IMG_START - act_size(16)
#define NPAST 19          // valid past kv_m: {0,1,2,3,5..19}
#define MAXPAST ((WIN - 1) * NPAST)   // 133

#define SCALE 0.17677669529663689f    // 1/sqrt(32)

#define THREADS 448       // 2 threads per query, 16 dims each; 432 active

// smem layout (floats)
#define OFF_SK 0
#define OFF_SV (FPT * DD)                    // 6912
#define OFF_PK (2 * FPT * DD)                // 13824
#define OFF_PV (2 * FPT * DD + MAXPAST * DD) // 18080
#define SMEM_FLOATS (2 * FPT * DD + 2 * MAXPAST * DD)  // 22336
#define SMEM_BYTES (SMEM_FLOATS * 4)         // 89344

__global__ void __launch_bounds__(THREADS, 2)
eye_attn_kernel(const float* __restrict__ q,
                const float* __restrict__ k,
                const float* __restrict__ v,
                float* __restrict__ out)
{
    extern __shared__ float smem[];
    float* sK = smem + OFF_SK;
    float* sV = smem + OFF_SV;
    float* pK = smem + OFF_PK;
    float* pV = smem + OFF_PV;

    const int t = blockIdx.x;
    const int h = blockIdx.y;
    const int b = blockIdx.z;
    const int tid = threadIdx.x;

    const size_t bh_base = ((size_t)(b * HH + h)) * SS * DD;

    // ---- load same-t K/V tile (contiguous, coalesced) ----
    {
        const float4* kg4 = (const float4*)(k + bh_base + (size_t)t * FPT * DD);
        const float4* vg4 = (const float4*)(v + bh_base + (size_t)t * FPT * DD);
        float4* sK4 = (float4*)sK;
        float4* sV4 = (float4*)sV;
        for (int i = tid; i < FPT * DD / 4; i += THREADS) {
            sK4[i] = kg4[i];
            sV4[i] = vg4[i];
        }
    }

    // ---- load compacted past K/V rows ----
    const int npt = (t < WIN - 1) ? t : (WIN - 1);   // # past timesteps
    {
        const int ntask = npt * NPAST * 8;           // 8 float4 per row
        for (int r4 = tid; r4 < ntask; r4 += THREADS) {
            const int r  = r4 >> 3;
            const int c  = r4 & 7;
            const int dt = r / NPAST + 1;
            const int i  = r - (dt - 1) * NPAST;
            const int m  = (i < 4) ? i : (i + 1);    // skip proprio m==4
            const size_t src = bh_base + ((size_t)(t - dt) * FPT + m) * DD;
            ((float4*)pK)[r * 8 + c] = ((const float4*)(k + src))[c];
            ((float4*)pV)[r * 8 + c] = ((const float4*)(v + src))[c];
        }
    }

    __syncthreads();

    // Each query is handled by 2 adjacent lanes: half=0 -> dims 0..15, half=1 -> dims 16..31
    const bool do_store = (tid < 2 * FPT);
    const int qi   = do_store ? (tid >> 1) : (FPT - 1);   // clamp idle lanes (redundant compute)
    const int half = tid & 1;
    const int dbase = half * 16;       // first dim of this thread's half (in floats)

    const bool is_img   = (qi >= IMG_START);
    const bool is_joint = (qi >= JOINT_START) && (qi < IMG_START);

    // load this thread's half of the q row, pre-scaled
    float qv[16];
    {
        const float4* qg4 = (const float4*)(q + bh_base + ((size_t)t * FPT + qi) * DD + dbase);
        #pragma unroll
        for (int i = 0; i < 4; i++) {
            float4 x = qg4[i];
            qv[4 * i + 0] = x.x * SCALE;
            qv[4 * i + 1] = x.y * SCALE;
            qv[4 * i + 2] = x.z * SCALE;
            qv[4 * i + 3] = x.w * SCALE;
        }
    }

    float acc[16];
    #pragma unroll
    for (int d = 0; d < 16; d++) acc[d] = 0.0f;
    float lsum = 0.0f;

    // one key: half-dot, pair-combine via shfl, exp, predicated accumulate
    auto doKey = [&](const float* krow, const float* vrow, bool valid) {
        const float4* k4 = (const float4*)(krow + dbase);
        float s0 = 0.f, s1 = 0.f, s2 = 0.f, s3 = 0.f;
        #pragma unroll
        for (int i = 0; i < 4; i++) {
            float4 kk = k4[i];
            s0 = fmaf(qv[4 * i + 0], kk.x, s0);
            s1 = fmaf(qv[4 * i + 1], kk.y, s1);
            s2 = fmaf(qv[4 * i + 2], kk.z, s2);
            s3 = fmaf(qv[4 * i + 3], kk.w, s3);
        }
        float s = (s0 + s1) + (s2 + s3);
        s += __shfl_xor_sync(0xFFFFFFFFu, s, 1);
        float p = valid ? __expf(s) : 0.0f;
        lsum += p;
        const float4* v4 = (const float4*)(vrow + dbase);
        #pragma unroll
        for (int i = 0; i < 4; i++) {
            float4 vv = v4[i];
            acc[4 * i + 0] = fmaf(p, vv.x, acc[4 * i + 0]);
            acc[4 * i + 1] = fmaf(p, vv.y, acc[4 * i + 1]);
            acc[4 * i + 2] = fmaf(p, vv.z, acc[4 * i + 2]);
            acc[4 * i + 3] = fmaf(p, vv.w, acc[4 * i + 3]);
        }
    };

    // Phase A: same-t keys 0..19 (valid for every query)
    #pragma unroll 4
    for (int j = 0; j < IMG_START; j++)
        doKey(sK + j * DD, sV + j * DD, true);

    // Phase B: same-t keys 20..215 (blocked for img queries). All-img warps skip.
    if (!is_img) {
        #pragma unroll 4
        for (int j = IMG_START; j < FPT; j++)
            doKey(sK + j * DD, sV + j * DD, true);
    }

    // Phase C: past keys (compacted). Joint queries only see past i<4 (m 0..3).
    {
        const int np = npt * NPAST;
        int i = 0;
        for (int r = 0; r < np; r++) {
            const bool valid = (!is_joint) | (i < 4);
            doKey(pK + r * DD, pV + r * DD, valid);
            if (++i == NPAST) i = 0;
        }
    }

    // ---- write out (this thread's 16 dims) ----
    if (do_store) {
        const float inv = 1.0f / lsum;
        float4* og4 = (float4*)(out + bh_base + ((size_t)t * FPT + qi) * DD + dbase);
        #pragma unroll
        for (int i = 0; i < 4; i++) {
            float4 o;
            o.x = acc[4 * i + 0] * inv;
            o.y = acc[4 * i + 1] * inv;
            o.z = acc[4 * i + 2] * inv;
            o.w = acc[4 * i + 3] * inv;
            og4[i] = o;
        }
    }
}

extern "C" void kernel_launch(void* const* d_in, const int* in_sizes, int n_in,
                              void* d_out, int out_size)
{
    const float* q = (const float*)d_in[0];
    const float* k = (const float*)d_in[1];
    const float* v = (const float*)d_in[2];
    float* out = (float*)d_out;

    cudaFuncSetAttribute(eye_attn_kernel,
                         cudaFuncAttributeMaxDynamicSharedMemorySize, SMEM_BYTES);

    dim3 grid(NT, HH, BB);   // (16, 12, 2)
    eye_attn_kernel<<<grid, THREADS, SMEM_BYTES>>>(q, k, v, out);
}

// round 3
// speedup vs baseline: 1.4722x; 1.4722x over previous
#include <cuda_runtime.h>
#include <cuda_bf16.h>
#include <math.h>

typedef unsigned long long u64;

// Problem constants (fixed by the dataset)
#define BB 2
#define HH 12
#define SS 3456
#define DD 32
#define FPT 216           // feats per timestep
#define NT (SS / FPT)     // 16 timesteps
#define WIN 8
#define IMG_START 20      // FPT - img_feat_size(196)
#define JOINT_START 4     // IMG_START - act_size(16)
#define NPAST 19          // valid past kv_m: {0,1,2,3,5..19}
#define MAXPAST ((WIN - 1) * NPAST)   // 133

// scale * log2(e): ex2.approx(dot) == exp(dot/sqrt(32))
#define SCL2E (0.17677669529663689f * 1.4426950408889634f)

#define THREADS 288       // 216 mains + 40 B-helpers + 32 C-helpers

// smem layout (floats)
#define OFF_SK 0
#define OFF_SV (FPT * DD)                    // 6912
#define OFF_PK (2 * FPT * DD)                // 13824
#define OFF_PV (2 * FPT * DD + MAXPAST * DD) // 18080
#define TILE_FLOATS (2 * FPT * DD + 2 * MAXPAST * DD)  // 22336
#define TILE_BYTES (TILE_FLOATS * 4)         // 89344 (u64-aligned)
#define NPART 72                             // 40 B + 32 C partials
#define PART_STRIDE 17                       // u64 per slot (16 acc + lsum)
#define SMEM_BYTES (TILE_BYTES + NPART * PART_STRIDE * 8)  // 99136

__device__ __forceinline__ u64 fma2(u64 a, u64 b, u64 c) {
    u64 d; asm("fma.rn.f32x2 %0, %1, %2, %3;" : "=l"(d) : "l"(a), "l"(b), "l"(c)); return d;
}
__device__ __forceinline__ u64 pack2(float lo, float hi) {
    u64 d; asm("mov.b64 %0, {%1, %2};" : "=l"(d) : "f"(lo), "f"(hi)); return d;
}
__device__ __forceinline__ void unpack2(u64 a, float& lo, float& hi) {
    asm("mov.b64 {%0, %1}, %2;" : "=f"(lo), "=f"(hi) : "l"(a));
}
__device__ __forceinline__ float ex2(float x) {
    float r; asm("ex2.approx.f32 %0, %1;" : "=f"(r) : "f"(x)); return r;
}

__global__ void __launch_bounds__(THREADS, 2)
eye_attn_kernel(const float* __restrict__ q,
                const float* __restrict__ k,
                const float* __restrict__ v,
                float* __restrict__ out)
{
    extern __shared__ float smem[];
    float* sK = smem + OFF_SK;
    float* sV = smem + OFF_SV;
    float* pK = smem + OFF_PK;
    float* pV = smem + OFF_PV;
    u64*   part = (u64*)((char*)smem + TILE_BYTES);

    const int t = blockIdx.x;
    const int h = blockIdx.y;
    const int b = blockIdx.z;
    const int tid = threadIdx.x;

    const size_t bh_base = ((size_t)(b * HH + h)) * SS * DD;

    // ---- load same-t K/V tile (contiguous, coalesced) ----
    {
        const float4* kg4 = (const float4*)(k + bh_base + (size_t)t * FPT * DD);
        const float4* vg4 = (const float4*)(v + bh_base + (size_t)t * FPT * DD);
        float4* sK4 = (float4*)sK;
        float4* sV4 = (float4*)sV;
        for (int i = tid; i < FPT * DD / 4; i += THREADS) {
            sK4[i] = kg4[i];
            sV4[i] = vg4[i];
        }
    }

    // ---- load compacted past K/V rows ----
    const int npt = (t < WIN - 1) ? t : (WIN - 1);   // # past timesteps
    {
        const int ntask = npt * NPAST * 8;           // 8 float4 per row
        for (int r4 = tid; r4 < ntask; r4 += THREADS) {
            const int r  = r4 >> 3;
            const int c  = r4 & 7;
            const int dt = r / NPAST + 1;
            const int i  = r - (dt - 1) * NPAST;
            const int m  = (i < 4) ? i : (i + 1);    // skip proprio m==4
            const size_t src = bh_base + ((size_t)(t - dt) * FPT + m) * DD;
            ((float4*)pK)[r * 8 + c] = ((const float4*)(k + src))[c];
            ((float4*)pV)[r * 8 + c] = ((const float4*)(v + src))[c];
        }
    }

    __syncthreads();

    // ---- thread roles ----
    // tid   0..215 : main for query tid. Phase A (20 same-t keys); queries >=32 also
    //                do their own past keys. Queries 0..31 get past keys from C-helpers;
    //                queries 0..19 get same-t keys 20..215 from two B-helpers each.
    // tid 216..255 : B-helper idx=tid-216; query j=idx>>1; half=idx&1 -> 98 same-t keys.
    // tid 256..287 : C-helper for query h=tid-256 (0..31): past keys, joint-predicated.
    const bool is_main = (tid < 2 * FPT / 2) && (tid < FPT);
    const bool is_bh   = (tid >= FPT) && (tid < FPT + 40);
    const int  bh_idx  = tid - FPT;          // for B-helpers
    const int  ch_idx  = tid - (FPT + 40);   // for C-helpers

    int qrow;
    if (tid < FPT)            qrow = tid;
    else if (is_bh)           qrow = bh_idx >> 1;
    else                      qrow = ch_idx;

    // main phase parameters
    const float* mkp;  const float* mvp;  int mn;  bool mjoint;
    if (tid < FPT) {
        if (tid < 32) { mkp = pK; mvp = pV; mn = 0; mjoint = false; }          // delegated
        else          { mkp = pK; mvp = pV; mn = npt * NPAST; mjoint = false; } // img: own past keys
    } else if (is_bh) {
        const int half = bh_idx & 1;
        mkp = sK + (IMG_START + half * 98) * DD;
        mvp = sV + (IMG_START + half * 98) * DD;
        mn = 98; mjoint = false;
    } else {
        mkp = pK; mvp = pV; mn = npt * NPAST;
        mjoint = (qrow >= JOINT_START) && (qrow < IMG_START);
    }
    const int nA = (tid < FPT) ? IMG_START : 0;   // helpers skip phase A

    // ---- load q row, pre-scaled by scale*log2e, packed f32x2 ----
    u64 q2[16];
    {
        const float4* qg4 = (const float4*)(q + bh_base + ((size_t)t * FPT + qrow) * DD);
        #pragma unroll
        for (int i = 0; i < 8; i++) {
            float4 x = qg4[i];
            q2[2 * i]     = pack2(x.x * SCL2E, x.y * SCL2E);
            q2[2 * i + 1] = pack2(x.z * SCL2E, x.w * SCL2E);
        }
    }

    u64 acc[16];
    #pragma unroll
    for (int i = 0; i < 16; i++) acc[i] = 0ull;
    float lsum = 0.0f;
    const u64 one2 = pack2(1.0f, 1.0f);

    // process n keys from (kbase, vbase); jointPred masks wrap-counter positions >= 4
    auto do_keys = [&](const float* kbase, const float* vbase, int n, bool jointPred) {
        int iw = 0;
        #pragma unroll 2
        for (int r = 0; r < n; ++r) {
            const ulonglong2* k2 = (const ulonglong2*)(kbase + r * DD);
            u64 sA = 0ull, sB = 0ull, sC = 0ull, sD = 0ull;
            ulonglong2 kk;
            kk = k2[0]; sA = fma2(q2[0],  kk.x, sA); sB = fma2(q2[1],  kk.y, sB);
            kk = k2[1]; sC = fma2(q2[2],  kk.x, sC); sD = fma2(q2[3],  kk.y, sD);
            kk = k2[2]; sA = fma2(q2[4],  kk.x, sA); sB = fma2(q2[5],  kk.y, sB);
            kk = k2[3]; sC = fma2(q2[6],  kk.x, sC); sD = fma2(q2[7],  kk.y, sD);
            kk = k2[4]; sA = fma2(q2[8],  kk.x, sA); sB = fma2(q2[9],  kk.y, sB);
            kk = k2[5]; sC = fma2(q2[10], kk.x, sC); sD = fma2(q2[11], kk.y, sD);
            kk = k2[6]; sA = fma2(q2[12], kk.x, sA); sB = fma2(q2[13], kk.y, sB);
            kk = k2[7]; sC = fma2(q2[14], kk.x, sC); sD = fma2(q2[15], kk.y, sD);
            u64 sAB = fma2(sA, one2, sB);
            u64 sCD = fma2(sC, one2, sD);
            u64 sT  = fma2(sAB, one2, sCD);
            float lo, hi; unpack2(sT, lo, hi);
            float e = ex2(lo + hi);
            bool valid = !jointPred || (iw < 4);
            float p = valid ? e : 0.0f;
            lsum += p;
            u64 p2 = pack2(p, p);
            const ulonglong2* v2 = (const ulonglong2*)(vbase + r * DD);
            ulonglong2 vv;
            vv = v2[0]; acc[0]  = fma2(p2, vv.x, acc[0]);  acc[1]  = fma2(p2, vv.y, acc[1]);
            vv = v2[1]; acc[2]  = fma2(p2, vv.x, acc[2]);  acc[3]  = fma2(p2, vv.y, acc[3]);
            vv = v2[2]; acc[4]  = fma2(p2, vv.x, acc[4]);  acc[5]  = fma2(p2, vv.y, acc[5]);
            vv = v2[3]; acc[6]  = fma2(p2, vv.x, acc[6]);  acc[7]  = fma2(p2, vv.y, acc[7]);
            vv = v2[4]; acc[8]  = fma2(p2, vv.x, acc[8]);  acc[9]  = fma2(p2, vv.y, acc[9]);
            vv = v2[5]; acc[10] = fma2(p2, vv.x, acc[10]); acc[11] = fma2(p2, vv.y, acc[11]);
            vv = v2[6]; acc[12] = fma2(p2, vv.x, acc[12]); acc[13] = fma2(p2, vv.y, acc[13]);
            vv = v2[7]; acc[14] = fma2(p2, vv.x, acc[14]); acc[15] = fma2(p2, vv.y, acc[15]);
            if (++iw == NPAST) iw = 0;
        }
    };

    // Phase A: same-t keys 0..19 (mains only; helper warps skip uniformly)
    if (nA > 0) do_keys(sK, sV, nA, false);

    // Phase B (warp0 queries 0..19 delegated -> mn=0 there):
    // mains 0..19 additionally own NOTHING else; queries 0..19 same-t img-window
    // keys are done by B-helpers. Note: queries 0..19 also see same-t keys 20..215.
    // (handled by B-helpers), queries 20..215 (img) skip them (img_to_img).

    // Main/helper bulk phase
    if (mn > 0) do_keys(mkp, mvp, mn, mjoint);

    // helpers publish partials
    if (tid >= FPT) {
        const int slot = is_bh ? bh_idx : (40 + ch_idx);
        u64* pp = part + slot * PART_STRIDE;
        #pragma unroll
        for (int i = 0; i < 16; i++) pp[i] = acc[i];
        ((float*)pp)[32] = lsum;
    }

    __syncthreads();

    if (tid < FPT) {
        if (tid < 32) {
            // add C-helper partial (past keys)
            {
                u64* pp = part + (40 + tid) * PART_STRIDE;
                #pragma unroll
                for (int i = 0; i < 16; i++) acc[i] = fma2(pp[i], one2, acc[i]);
                lsum += ((float*)pp)[32];
            }
            if (tid < IMG_START) {
                // add two B-helper partials (same-t keys 20..215)
                #pragma unroll
                for (int hB = 0; hB < 2; hB++) {
                    u64* pp = part + (2 * tid + hB) * PART_STRIDE;
                    #pragma unroll
                    for (int i = 0; i < 16; i++) acc[i] = fma2(pp[i], one2, acc[i]);
                    lsum += ((float*)pp)[32];
                }
            }
        }
        // ---- write out ----
        const float inv = 1.0f / lsum;
        float4* og4 = (float4*)(out + bh_base + ((size_t)t * FPT + tid) * DD);
        #pragma unroll
        for (int i = 0; i < 8; i++) {
            float a0, a1, a2, a3;
            unpack2(acc[2 * i], a0, a1);
            unpack2(acc[2 * i + 1], a2, a3);
            float4 o;
            o.x = a0 * inv; o.y = a1 * inv; o.z = a2 * inv; o.w = a3 * inv;
            og4[i] = o;
        }
    }
}

extern "C" void kernel_launch(void* const* d_in, const int* in_sizes, int n_in,
                              void* d_out, int out_size)
{
    const float* q = (const float*)d_in[0];
    const float* k = (const float*)d_in[1];
    const float* v = (const float*)d_in[2];
    float* out = (float*)d_out;

    cudaFuncSetAttribute(eye_attn_kernel,
                         cudaFuncAttributeMaxDynamicSharedMemorySize, SMEM_BYTES);

    dim3 grid(NT, HH, BB);   // (16, 12, 2)
    eye_attn_kernel<<<grid, THREADS, SMEM_BYTES>>>(q, k, v, out);
}